// round 2
// baseline (speedup 1.0000x reference)
#include <cuda_runtime.h>
#include <math.h>

// ---------------- problem constants ----------------
#define HDIM 2048
#define FDIM 4096            // 2*H
#define NTOK 8192            // 4*2048 tokens

// ---------------- GEMM tiling ----------------
#define BM 128
#define BN 128
#define BK 16
#define TM 8
#define TN 8
#define NTHREADS 256

enum { ACT_GELU = 0, ACT_RELU = 1, ACT_NONE = 2 };

// ---------------- device scratch (static globals; no allocation) ----------------
__device__ int   g_cnt[2];
__device__ int   g_list[2][NTOK];                 // slot -> token
__device__ float g_Xc[2][NTOK][HDIM];             // gathered x rows per expert
__device__ float g_Hc[2][NTOK][FDIM];             // hidden activations per expert

// ---------------- kernel 1: zero counters ----------------
__global__ void zero_counts_kernel() {
    if (threadIdx.x < 2) g_cnt[threadIdx.x] = 0;
}

// ---------------- kernel 2: gate (argmax of logits) + compact + gather ----------------
// one warp per token; 8 warps per block
__global__ void gate_gather_kernel(const float* __restrict__ x,
                                   const float* __restrict__ Wg) {
    __shared__ float wg[2 * HDIM];
    for (int i = threadIdx.x; i < 2 * HDIM; i += blockDim.x) wg[i] = Wg[i];
    __syncthreads();

    const int warp = threadIdx.x >> 5;
    const int lane = threadIdx.x & 31;
    const int token = blockIdx.x * 8 + warp;
    const float* xr = x + (size_t)token * HDIM;

    float s0 = 0.f, s1 = 0.f;
    for (int i = lane; i < HDIM; i += 32) {
        float v = xr[i];
        s0 += v * wg[i];
        s1 += v * wg[HDIM + i];
    }
    #pragma unroll
    for (int o = 16; o > 0; o >>= 1) {
        s0 += __shfl_xor_sync(0xffffffffu, s0, o);
        s1 += __shfl_xor_sync(0xffffffffu, s1, o);
    }
    // softmax is monotone: argmax(softmax) == argmax(logits); ties -> expert 0 (jnp.argmax)
    const int e = (s1 > s0) ? 1 : 0;

    int pos = 0;
    if (lane == 0) pos = atomicAdd(&g_cnt[e], 1);
    pos = __shfl_sync(0xffffffffu, pos, 0);
    if (lane == 0) g_list[e][pos] = token;

    // gather row into compact per-expert buffer (float4)
    float4*       dst = reinterpret_cast<float4*>(&g_Xc[e][pos][0]);
    const float4* src = reinterpret_cast<const float4*>(xr);
    #pragma unroll
    for (int i = lane; i < HDIM / 4; i += 32) dst[i] = src[i];
}

// ---------------- kernel 3/4: NT SGEMM, fused bias+activation, optional scatter ----------------
// C[m,n] = sum_k A[m,k] * B[n,k]  (A and B both row-major with K contiguous)
// up   (DOWN=false): A = g_Xc[e], C = g_Hc[e] (ldc = FDIM = N)
// down (DOWN=true) : A = g_Hc[e], C = out row scattered to token = g_list[e][m]
template <int K, int N, int ACT, bool DOWN>
__global__ void __launch_bounds__(NTHREADS, 2)
expert_gemm_kernel(int e,
                   const float* __restrict__ Bw,
                   const float* __restrict__ bias,
                   float* __restrict__ out) {
    const int cnt = g_cnt[e];
    const int m0 = blockIdx.y * BM;
    if (m0 >= cnt) return;
    const int n0 = blockIdx.x * BN;

    const float* A = DOWN ? &g_Hc[e][0][0] : &g_Xc[e][0][0];

    __shared__ float As[2][BK][BM];
    __shared__ float Bs[2][BK][BN];

    const int tid = threadIdx.x;
    const int lr = tid >> 1;            // 0..127 : row within tile for loads
    const int lc = (tid & 1) * 8;       // 0 or 8 : k-offset for loads (2x float4)

    const float* Ap = A  + (size_t)(m0 + lr) * K + lc;
    const float* Bp = Bw + (size_t)(n0 + lr) * K + lc;
    const bool aval = (m0 + lr) < cnt;

    float4 a0, a1, b0, b1;
    auto load_tile = [&](int k0) {
        if (aval) {
            a0 = *reinterpret_cast<const float4*>(Ap + k0);
            a1 = *reinterpret_cast<const float4*>(Ap + k0 + 4);
        } else {
            a0 = make_float4(0.f, 0.f, 0.f, 0.f);
            a1 = make_float4(0.f, 0.f, 0.f, 0.f);
        }
        b0 = *reinterpret_cast<const float4*>(Bp + k0);
        b1 = *reinterpret_cast<const float4*>(Bp + k0 + 4);
    };
    auto store_tile = [&](int buf) {
        As[buf][lc + 0][lr] = a0.x; As[buf][lc + 1][lr] = a0.y;
        As[buf][lc + 2][lr] = a0.z; As[buf][lc + 3][lr] = a0.w;
        As[buf][lc + 4][lr] = a1.x; As[buf][lc + 5][lr] = a1.y;
        As[buf][lc + 6][lr] = a1.z; As[buf][lc + 7][lr] = a1.w;
        Bs[buf][lc + 0][lr] = b0.x; Bs[buf][lc + 1][lr] = b0.y;
        Bs[buf][lc + 2][lr] = b0.z; Bs[buf][lc + 3][lr] = b0.w;
        Bs[buf][lc + 4][lr] = b1.x; Bs[buf][lc + 5][lr] = b1.y;
        Bs[buf][lc + 6][lr] = b1.z; Bs[buf][lc + 7][lr] = b1.w;
    };

    load_tile(0);
    store_tile(0);
    __syncthreads();

    const int tx = tid & 15;   // 16 threads across N
    const int ty = tid >> 4;   // 16 threads across M

    float acc[TM][TN];
    #pragma unroll
    for (int i = 0; i < TM; i++)
        #pragma unroll
        for (int j = 0; j < TN; j++) acc[i][j] = 0.f;

    const int NT = K / BK;
    for (int t = 0; t < NT; t++) {
        const int cur = t & 1;
        if (t + 1 < NT) load_tile((t + 1) * BK);

        #pragma unroll
        for (int kk = 0; kk < BK; kk++) {
            float ra[TM], rb[TN];
            #pragma unroll
            for (int i = 0; i < TM; i++) ra[i] = As[cur][kk][ty * TM + i];
            #pragma unroll
            for (int j = 0; j < TN; j++) rb[j] = Bs[cur][kk][tx * TN + j];
            #pragma unroll
            for (int i = 0; i < TM; i++)
                #pragma unroll
                for (int j = 0; j < TN; j++) acc[i][j] += ra[i] * rb[j];
        }

        if (t + 1 < NT) store_tile(cur ^ 1);
        __syncthreads();
    }

    // epilogue: bias + activation (+scatter)
    #pragma unroll
    for (int i = 0; i < TM; i++) {
        const int m = m0 + ty * TM + i;
        if (m >= cnt) continue;
        float* crow;
        if (DOWN) {
            const int tok = g_list[e][m];
            crow = out + (size_t)tok * N + n0 + tx * TN;
        } else {
            crow = &g_Hc[e][m][0] + n0 + tx * TN;
        }
        float v[TN];
        #pragma unroll
        for (int j = 0; j < TN; j++) {
            float t2 = acc[i][j] + bias[n0 + tx * TN + j];
            if (ACT == ACT_GELU) t2 = 0.5f * t2 * (1.0f + erff(t2 * 0.70710678118654752f));
            else if (ACT == ACT_RELU) t2 = fmaxf(t2, 0.0f);
            v[j] = t2;
        }
        *reinterpret_cast<float4*>(crow)     = make_float4(v[0], v[1], v[2], v[3]);
        *reinterpret_cast<float4*>(crow + 4) = make_float4(v[4], v[5], v[6], v[7]);
    }
}

// ---------------- launch ----------------
extern "C" void kernel_launch(void* const* d_in, const int* in_sizes, int n_in,
                              void* d_out, int out_size) {
    const float* x   = (const float*)d_in[0];
    const float* Wg  = (const float*)d_in[1];
    const float* W0a = (const float*)d_in[2];
    const float* b0a = (const float*)d_in[3];
    const float* W0b = (const float*)d_in[4];
    const float* b0b = (const float*)d_in[5];
    const float* W1a = (const float*)d_in[6];
    const float* b1a = (const float*)d_in[7];
    const float* W1b = (const float*)d_in[8];
    const float* b1b = (const float*)d_in[9];
    float* out = (float*)d_out;

    zero_counts_kernel<<<1, 32>>>();
    gate_gather_kernel<<<NTOK / 8, 256>>>(x, Wg);

    dim3 gridUp(FDIM / BN, NTOK / BM);    // (32, 64)
    dim3 gridDn(HDIM / BN, NTOK / BM);    // (16, 64)

    // up projections (fused bias + activation) -> g_Hc[e]
    expert_gemm_kernel<HDIM, FDIM, ACT_GELU, false><<<gridUp, NTHREADS>>>(0, W0a, b0a, nullptr);
    expert_gemm_kernel<HDIM, FDIM, ACT_RELU, false><<<gridUp, NTHREADS>>>(1, W1a, b1a, nullptr);

    // down projections (fused bias, scatter to out[token])
    expert_gemm_kernel<FDIM, HDIM, ACT_NONE, true><<<gridDn, NTHREADS>>>(0, W0b, b0b, out);
    expert_gemm_kernel<FDIM, HDIM, ACT_NONE, true><<<gridDn, NTHREADS>>>(1, W1b, b1b, out);
}

// round 4
// speedup vs baseline: 2.8992x; 2.8992x over previous
#include <cuda_runtime.h>
#include <cuda_bf16.h>
#include <math.h>
#include <stdint.h>

// ---------------- problem constants ----------------
#define HDIM 2048
#define FDIM 4096
#define NTOK 8192

// ---------------- GEMM tiling ----------------
#define BM 128
#define BN 128
#define BK 32               // bf16 elements per k-chunk
#define GTHREADS 256        // 8 warps: 2 (M) x 4 (N)

enum { ACT_GELU = 0, ACT_RELU = 1, ACT_NONE = 2 };

// ---------------- device scratch (static globals; no allocation) ----------------
__device__ int g_cnt[2];
__device__ int g_list[2][NTOK];
__device__ __align__(128) __nv_bfloat16 g_Xh[2][NTOK][HDIM];
__device__ __align__(128) __nv_bfloat16 g_Xl[2][NTOK][HDIM];
__device__ __align__(128) __nv_bfloat16 g_Hh[2][NTOK][FDIM];
__device__ __align__(128) __nv_bfloat16 g_Hl[2][NTOK][FDIM];
__device__ __align__(128) __nv_bfloat16 g_Wah[2][FDIM][HDIM];
__device__ __align__(128) __nv_bfloat16 g_Wal[2][FDIM][HDIM];
__device__ __align__(128) __nv_bfloat16 g_Wbh[2][HDIM][FDIM];
__device__ __align__(128) __nv_bfloat16 g_Wbl[2][HDIM][FDIM];

// ---------------- PTX helpers (all plain sm_80+ features) ----------------
__device__ __forceinline__ void cpa16(uint32_t dst, const void* src) {
    asm volatile("cp.async.cg.shared.global [%0], [%1], 16;" :: "r"(dst), "l"(src));
}
__device__ __forceinline__ void ldsm4(uint32_t* r, uint32_t addr) {
    asm volatile("ldmatrix.sync.aligned.m8n8.x4.shared.b16 {%0,%1,%2,%3}, [%4];"
                 : "=r"(r[0]), "=r"(r[1]), "=r"(r[2]), "=r"(r[3]) : "r"(addr));
}
__device__ __forceinline__ void mma16816(float* c, const uint32_t* a, const uint32_t* b) {
    asm volatile("mma.sync.aligned.m16n8k16.row.col.f32.bf16.bf16.f32 "
                 "{%0,%1,%2,%3}, {%4,%5,%6,%7}, {%8,%9}, {%0,%1,%2,%3};"
                 : "+f"(c[0]), "+f"(c[1]), "+f"(c[2]), "+f"(c[3])
                 : "r"(a[0]), "r"(a[1]), "r"(a[2]), "r"(a[3]), "r"(b[0]), "r"(b[1]));
}

// smem tile layout: [128 rows][32 bf16] stored as 64 "lines" of 128B (2 rows/line),
// 8 x 16B chunks per line, chunk ^= (line & 7)  -> ldmatrix & cp.async conflict-free
__device__ __forceinline__ uint32_t smem_off(int row, int kc /*16B chunk 0..3*/) {
    int line = row >> 1;
    int ch = ((row & 1) << 2) | kc;
    ch ^= (line & 7);
    return (uint32_t)(line * 128 + ch * 16);
}

// ---------------- kernel: zero counters ----------------
__global__ void zero_counts_kernel() {
    if (threadIdx.x < 2) g_cnt[threadIdx.x] = 0;
}

// ---------------- kernel: gate + compact + gather + bf16 split ----------------
__global__ void gate_gather_kernel(const float* __restrict__ x,
                                   const float* __restrict__ Wg) {
    __shared__ float wg[2 * HDIM];
    for (int i = threadIdx.x; i < 2 * HDIM; i += blockDim.x) wg[i] = Wg[i];
    __syncthreads();

    const int warp = threadIdx.x >> 5;
    const int lane = threadIdx.x & 31;
    const int token = blockIdx.x * 8 + warp;
    const float* xr = x + (size_t)token * HDIM;

    float s0 = 0.f, s1 = 0.f;
    for (int i = lane; i < HDIM; i += 32) {
        float v = xr[i];
        s0 += v * wg[i];
        s1 += v * wg[HDIM + i];
    }
    #pragma unroll
    for (int o = 16; o > 0; o >>= 1) {
        s0 += __shfl_xor_sync(0xffffffffu, s0, o);
        s1 += __shfl_xor_sync(0xffffffffu, s1, o);
    }
    const int e = (s1 > s0) ? 1 : 0;   // argmax(softmax)==argmax(logits); ties -> 0

    int pos = 0;
    if (lane == 0) pos = atomicAdd(&g_cnt[e], 1);
    pos = __shfl_sync(0xffffffffu, pos, 0);
    if (lane == 0) g_list[e][pos] = token;

    for (int i = lane; i < HDIM; i += 32) {
        float v = xr[i];
        __nv_bfloat16 h = __float2bfloat16(v);
        g_Xh[e][pos][i] = h;
        g_Xl[e][pos][i] = __float2bfloat16(v - __bfloat162float(h));
    }
}

// ---------------- kernel: weight split fp32 -> bf16 hi/lo ----------------
__global__ void wsplit_kernel(const float* __restrict__ src, int sel, int e) {
    const size_t i = ((size_t)blockIdx.x * 256 + threadIdx.x) * 4;
    float4 v = *reinterpret_cast<const float4*>(src + i);
    __nv_bfloat16* H = sel ? &g_Wbh[e][0][0] : &g_Wah[e][0][0];
    __nv_bfloat16* L = sel ? &g_Wbl[e][0][0] : &g_Wal[e][0][0];
    float vv[4] = {v.x, v.y, v.z, v.w};
    #pragma unroll
    for (int j = 0; j < 4; j++) {
        __nv_bfloat16 h = __float2bfloat16(vv[j]);
        H[i + j] = h;
        L[i + j] = __float2bfloat16(vv[j] - __bfloat162float(h));
    }
}

// ---------------- kernel: split-bf16 mma.sync GEMM ----------------
// C[m,n] = sum_k A[m,k]*B[n,k], fp32 accum, via AhBh + AhBl + AlBh
template <int K, int ACT, bool DOWN>
__global__ void __launch_bounds__(GTHREADS, 1)
moe_gemm(int e, const float* __restrict__ bias, float* __restrict__ out) {
    const int cnt = g_cnt[e];
    const int m0 = blockIdx.y * BM;
    if (m0 >= cnt) return;
    const int n0 = blockIdx.x * BN;

    extern __shared__ char smem[];
    const uint32_t sb = (uint32_t)__cvta_generic_to_shared(smem);

    const int tid = threadIdx.x;
    const int lane = tid & 31;
    const int warp = tid >> 5;
    const int wm = warp >> 2;          // 0..1  (64 rows each)
    const int wn = warp & 3;           // 0..3  (32 cols each)
    const int g = lane >> 3;           // ldmatrix lane group

    const __nv_bfloat16* Ah = DOWN ? &g_Hh[e][0][0] : &g_Xh[e][0][0];
    const __nv_bfloat16* Al = DOWN ? &g_Hl[e][0][0] : &g_Xl[e][0][0];
    const __nv_bfloat16* Bh = DOWN ? &g_Wbh[e][0][0] : &g_Wah[e][0][0];
    const __nv_bfloat16* Bl = DOWN ? &g_Wbl[e][0][0] : &g_Wal[e][0][0];
    const __nv_bfloat16* srcs[4] = {Ah, Al, Bh, Bl};

    // per-buffer: Ah 8K | Al 8K | Bh 8K | Bl 8K = 32KB; double buffered
    constexpr uint32_t BUFB = 32768u;
    constexpr uint32_t REG = 8192u;

    // cp.async fill of one buffer at k-offset k0
    auto fill = [&](int buf, int k0) {
        const uint32_t bb = sb + buf * BUFB;
        #pragma unroll
        for (int i = 0; i < 8; i++) {
            int idx = tid + i * 256;           // 0..2047
            int region = idx >> 9;             // 0..3
            int cid = idx & 511;
            int row = cid >> 2, kc = cid & 3;
            int grow = (region < 2) ? (m0 + row) : (n0 + row);
            const __nv_bfloat16* s = srcs[region] + (size_t)grow * K + k0 + kc * 8;
            cpa16(bb + region * REG + smem_off(row, kc), s);
        }
        asm volatile("cp.async.commit_group;" ::: "memory");
    };

    float acc[4][4][4];
    #pragma unroll
    for (int i = 0; i < 4; i++)
        #pragma unroll
        for (int j = 0; j < 4; j++)
            #pragma unroll
            for (int q = 0; q < 4; q++) acc[i][j][q] = 0.f;

    const int NT = K / BK;
    fill(0, 0);

    for (int t = 0; t < NT; t++) {
        const int buf = t & 1;
        if (t + 1 < NT) {
            fill(buf ^ 1, (t + 1) * BK);
            asm volatile("cp.async.wait_group 1;" ::: "memory");
        } else {
            asm volatile("cp.async.wait_group 0;" ::: "memory");
        }
        __syncthreads();

        const uint32_t bb = sb + buf * BUFB;
        #pragma unroll
        for (int ks = 0; ks < 2; ks++) {           // two k16 steps per BK=32
            const int kc = ks * 2;
            uint32_t ah[4][4], al[4][4], bh[2][4], bl[2][4];
            #pragma unroll
            for (int tm = 0; tm < 4; tm++) {
                int row = wm * 64 + tm * 16 + (g & 1) * 8 + (lane & 7);
                uint32_t o = smem_off(row, kc + (g >> 1));
                ldsm4(ah[tm], bb + o);
                ldsm4(al[tm], bb + REG + o);
            }
            #pragma unroll
            for (int tp = 0; tp < 2; tp++) {
                int row = wn * 32 + tp * 16 + (g >> 1) * 8 + (lane & 7);
                uint32_t o = smem_off(row, kc + (g & 1));
                ldsm4(bh[tp], bb + 2 * REG + o);
                ldsm4(bl[tp], bb + 3 * REG + o);
            }
            #pragma unroll
            for (int tm = 0; tm < 4; tm++)
                #pragma unroll
                for (int tn = 0; tn < 4; tn++) {
                    const uint32_t* bhf = &bh[tn >> 1][(tn & 1) * 2];
                    const uint32_t* blf = &bl[tn >> 1][(tn & 1) * 2];
                    mma16816(acc[tm][tn], ah[tm], bhf);
                    mma16816(acc[tm][tn], ah[tm], blf);
                    mma16816(acc[tm][tn], al[tm], bhf);
                }
        }
        __syncthreads();
    }

    // ---------------- epilogue: bias + activation, store from registers ----------------
    #pragma unroll
    for (int tm = 0; tm < 4; tm++) {
        #pragma unroll
        for (int half = 0; half < 2; half++) {       // c0c1 (row) / c2c3 (row+8)
            const int m = m0 + wm * 64 + tm * 16 + half * 8 + (lane >> 2);
            if (m >= cnt) continue;
            float* orow = nullptr;
            __nv_bfloat16 *hrow = nullptr, *lrow = nullptr;
            int tok;
            if (DOWN) {
                tok = g_list[e][m];
                orow = out + (size_t)tok * HDIM;
            } else {
                hrow = &g_Hh[e][m][0];
                lrow = &g_Hl[e][m][0];
            }
            #pragma unroll
            for (int tn = 0; tn < 4; tn++) {
                const int col = n0 + wn * 32 + tn * 8 + (lane & 3) * 2;
                #pragma unroll
                for (int q = 0; q < 2; q++) {
                    float v = acc[tm][tn][half * 2 + q] + bias[col + q];
                    if (ACT == ACT_GELU)
                        v = 0.5f * v * (1.0f + erff(v * 0.70710678118654752f));
                    else if (ACT == ACT_RELU)
                        v = fmaxf(v, 0.0f);
                    if (DOWN) {
                        orow[col + q] = v;
                    } else {
                        __nv_bfloat16 h = __float2bfloat16(v);
                        hrow[col + q] = h;
                        lrow[col + q] = __float2bfloat16(v - __bfloat162float(h));
                    }
                }
            }
        }
    }
}

// ---------------- launch ----------------
extern "C" void kernel_launch(void* const* d_in, const int* in_sizes, int n_in,
                              void* d_out, int out_size) {
    const float* x   = (const float*)d_in[0];
    const float* Wg  = (const float*)d_in[1];
    const float* W0a = (const float*)d_in[2];
    const float* b0a = (const float*)d_in[3];
    const float* W0b = (const float*)d_in[4];
    const float* b0b = (const float*)d_in[5];
    const float* W1a = (const float*)d_in[6];
    const float* b1a = (const float*)d_in[7];
    const float* W1b = (const float*)d_in[8];
    const float* b1b = (const float*)d_in[9];
    float* out = (float*)d_out;

    constexpr int SMEM_SZ = 2 * 32768;   // 64KB
    cudaFuncSetAttribute(moe_gemm<HDIM, ACT_GELU, false>,
                         cudaFuncAttributeMaxDynamicSharedMemorySize, SMEM_SZ);
    cudaFuncSetAttribute(moe_gemm<HDIM, ACT_RELU, false>,
                         cudaFuncAttributeMaxDynamicSharedMemorySize, SMEM_SZ);
    cudaFuncSetAttribute(moe_gemm<FDIM, ACT_NONE, true>,
                         cudaFuncAttributeMaxDynamicSharedMemorySize, SMEM_SZ);

    zero_counts_kernel<<<1, 32>>>();
    gate_gather_kernel<<<NTOK / 8, 256>>>(x, Wg);

    const int nWblk = (FDIM * HDIM / 4) / 256;
    wsplit_kernel<<<nWblk, 256>>>(W0a, 0, 0);
    wsplit_kernel<<<nWblk, 256>>>(W1a, 0, 1);
    wsplit_kernel<<<nWblk, 256>>>(W0b, 1, 0);
    wsplit_kernel<<<nWblk, 256>>>(W1b, 1, 1);

    dim3 gUp(FDIM / BN, NTOK / BM);   // (32, 64)
    dim3 gDn(HDIM / BN, NTOK / BM);   // (16, 64)
    moe_gemm<HDIM, ACT_GELU, false><<<gUp, GTHREADS, SMEM_SZ>>>(0, b0a, nullptr);
    moe_gemm<HDIM, ACT_RELU, false><<<gUp, GTHREADS, SMEM_SZ>>>(1, b1a, nullptr);
    moe_gemm<FDIM, ACT_NONE, true><<<gDn, GTHREADS, SMEM_SZ>>>(0, b0b, out);
    moe_gemm<FDIM, ACT_NONE, true><<<gDn, GTHREADS, SMEM_SZ>>>(1, b1b, out);
}

// round 5
// speedup vs baseline: 3.1149x; 1.0744x over previous
#include <cuda_runtime.h>
#include <cuda_bf16.h>
#include <math.h>
#include <stdint.h>

// ---------------- problem constants ----------------
#define HDIM 2048
#define FDIM 4096
#define NTOK 8192

// ---------------- GEMM tiling ----------------
#define BM 128
#define BN 128
#define BK 32               // bf16 elements per k-chunk
#define GTHREADS 256        // 8 warps: 2 (M) x 4 (N)

enum { ACT_GELU = 0, ACT_RELU = 1, ACT_NONE = 2 };

// ---------------- device scratch (static globals; no allocation) ----------------
__device__ int g_cnt[2];
__device__ int g_list[2][NTOK];
__device__ __align__(128) __nv_bfloat16 g_Xh[2][NTOK][HDIM];
__device__ __align__(128) __nv_bfloat16 g_Xl[2][NTOK][HDIM];
__device__ __align__(128) __nv_bfloat16 g_Hh[2][NTOK][FDIM];
__device__ __align__(128) __nv_bfloat16 g_Hl[2][NTOK][FDIM];
__device__ __align__(128) __nv_bfloat16 g_Wah[2][FDIM][HDIM];
__device__ __align__(128) __nv_bfloat16 g_Wal[2][FDIM][HDIM];
__device__ __align__(128) __nv_bfloat16 g_Wbh[2][HDIM][FDIM];
__device__ __align__(128) __nv_bfloat16 g_Wbl[2][HDIM][FDIM];

// ---------------- PTX helpers (plain sm_80+ features only) ----------------
__device__ __forceinline__ void cpa16(uint32_t dst, const void* src) {
    asm volatile("cp.async.cg.shared.global [%0], [%1], 16;" :: "r"(dst), "l"(src));
}
__device__ __forceinline__ void ldsm4(uint32_t* r, uint32_t addr) {
    asm volatile("ldmatrix.sync.aligned.m8n8.x4.shared.b16 {%0,%1,%2,%3}, [%4];"
                 : "=r"(r[0]), "=r"(r[1]), "=r"(r[2]), "=r"(r[3]) : "r"(addr));
}
__device__ __forceinline__ void mma16816(float* c, const uint32_t* a, const uint32_t* b) {
    asm volatile("mma.sync.aligned.m16n8k16.row.col.f32.bf16.bf16.f32 "
                 "{%0,%1,%2,%3}, {%4,%5,%6,%7}, {%8,%9}, {%0,%1,%2,%3};"
                 : "+f"(c[0]), "+f"(c[1]), "+f"(c[2]), "+f"(c[3])
                 : "r"(a[0]), "r"(a[1]), "r"(a[2]), "r"(a[3]), "r"(b[0]), "r"(b[1]));
}

// smem tile layout: [128 rows][32 bf16] as 64 lines of 128B (2 rows/line),
// 8 x 16B chunks per line, chunk ^= (line & 7) -> conflict-free ldmatrix + cp.async
__device__ __forceinline__ uint32_t smem_off(int row, int kc /*16B chunk 0..3*/) {
    int line = row >> 1;
    int ch = ((row & 1) << 2) | kc;
    ch ^= (line & 7);
    return (uint32_t)(line * 128 + ch * 16);
}

// ---------------- kernel: zero counters ----------------
__global__ void zero_counts_kernel() {
    if (threadIdx.x < 2) g_cnt[threadIdx.x] = 0;
}

// ---------------- kernel: gate + compact + gather + bf16 split ----------------
__global__ void gate_gather_kernel(const float* __restrict__ x,
                                   const float* __restrict__ Wg) {
    __shared__ float wg[2 * HDIM];
    for (int i = threadIdx.x; i < 2 * HDIM; i += blockDim.x) wg[i] = Wg[i];
    __syncthreads();

    const int warp = threadIdx.x >> 5;
    const int lane = threadIdx.x & 31;
    const int token = blockIdx.x * 8 + warp;
    const float* xr = x + (size_t)token * HDIM;

    float s0 = 0.f, s1 = 0.f;
    for (int i = lane; i < HDIM; i += 32) {
        float v = xr[i];
        s0 += v * wg[i];
        s1 += v * wg[HDIM + i];
    }
    #pragma unroll
    for (int o = 16; o > 0; o >>= 1) {
        s0 += __shfl_xor_sync(0xffffffffu, s0, o);
        s1 += __shfl_xor_sync(0xffffffffu, s1, o);
    }
    const int e = (s1 > s0) ? 1 : 0;   // argmax(softmax)==argmax(logits); ties -> 0

    int pos = 0;
    if (lane == 0) pos = atomicAdd(&g_cnt[e], 1);
    pos = __shfl_sync(0xffffffffu, pos, 0);
    if (lane == 0) g_list[e][pos] = token;

    for (int i = lane; i < HDIM; i += 32) {
        float v = xr[i];
        __nv_bfloat16 h = __float2bfloat16(v);
        g_Xh[e][pos][i] = h;
        g_Xl[e][pos][i] = __float2bfloat16(v - __bfloat162float(h));
    }
}

// ---------------- kernel: all-weights split fp32 -> bf16 hi/lo (one launch) ----------------
__global__ void wsplit_all_kernel(const float* __restrict__ W0a, const float* __restrict__ W1a,
                                  const float* __restrict__ W0b, const float* __restrict__ W1b) {
    const int which = blockIdx.y;
    const float* src;
    __nv_bfloat16 *H, *L;
    switch (which) {
        case 0: src = W0a; H = &g_Wah[0][0][0]; L = &g_Wal[0][0][0]; break;
        case 1: src = W1a; H = &g_Wah[1][0][0]; L = &g_Wal[1][0][0]; break;
        case 2: src = W0b; H = &g_Wbh[0][0][0]; L = &g_Wbl[0][0][0]; break;
        default: src = W1b; H = &g_Wbh[1][0][0]; L = &g_Wbl[1][0][0]; break;
    }
    const size_t i = ((size_t)blockIdx.x * 256 + threadIdx.x) * 4;
    float4 v = *reinterpret_cast<const float4*>(src + i);
    float vv[4] = {v.x, v.y, v.z, v.w};
    __nv_bfloat16 hh[4], ll[4];
    #pragma unroll
    for (int j = 0; j < 4; j++) {
        hh[j] = __float2bfloat16(vv[j]);
        ll[j] = __float2bfloat16(vv[j] - __bfloat162float(hh[j]));
    }
    *reinterpret_cast<uint2*>(H + i) = *reinterpret_cast<uint2*>(hh);
    *reinterpret_cast<uint2*>(L + i) = *reinterpret_cast<uint2*>(ll);
}

// ---------------- kernel: split-bf16 mma.sync GEMM ----------------
// C[m,n] = sum_k A[m,k]*B[n,k], fp32 accum, via AhBh + AhBl + AlBh (term-major order)
template <int K, int ACT, bool DOWN>
__global__ void __launch_bounds__(GTHREADS, 2)
moe_gemm(int e, const float* __restrict__ bias, float* __restrict__ out) {
    const int cnt = g_cnt[e];
    const int m0 = blockIdx.y * BM;
    if (m0 >= cnt) return;
    const int n0 = blockIdx.x * BN;

    extern __shared__ char smem[];
    const uint32_t sb = (uint32_t)__cvta_generic_to_shared(smem);

    const int tid = threadIdx.x;
    const int lane = tid & 31;
    const int warp = tid >> 5;
    const int wm = warp >> 2;          // 0..1  (64 rows each)
    const int wn = warp & 3;           // 0..3  (32 cols each)
    const int g = lane >> 3;           // ldmatrix lane group

    const __nv_bfloat16* Ah = DOWN ? &g_Hh[e][0][0] : &g_Xh[e][0][0];
    const __nv_bfloat16* Al = DOWN ? &g_Hl[e][0][0] : &g_Xl[e][0][0];
    const __nv_bfloat16* Bh = DOWN ? &g_Wbh[e][0][0] : &g_Wah[e][0][0];
    const __nv_bfloat16* Bl = DOWN ? &g_Wbl[e][0][0] : &g_Wal[e][0][0];
    const __nv_bfloat16* srcs[4] = {Ah, Al, Bh, Bl};

    // per-buffer: Ah 8K | Al 8K | Bh 8K | Bl 8K = 32KB; double buffered
    constexpr uint32_t BUFB = 32768u;
    constexpr uint32_t REG = 8192u;

    auto fill = [&](int buf, int k0) {
        const uint32_t bb = sb + buf * BUFB;
        #pragma unroll
        for (int i = 0; i < 8; i++) {
            int idx = tid + i * 256;           // 0..2047
            int region = idx >> 9;             // 0..3
            int cid = idx & 511;
            int row = cid >> 2, kc = cid & 3;
            int grow = (region < 2) ? (m0 + row) : (n0 + row);
            const __nv_bfloat16* s = srcs[region] + (size_t)grow * K + k0 + kc * 8;
            cpa16(bb + region * REG + smem_off(row, kc), s);
        }
        asm volatile("cp.async.commit_group;" ::: "memory");
    };

    float acc[4][4][4];
    #pragma unroll
    for (int i = 0; i < 4; i++)
        #pragma unroll
        for (int j = 0; j < 4; j++)
            #pragma unroll
            for (int q = 0; q < 4; q++) acc[i][j][q] = 0.f;

    const int NT = K / BK;
    fill(0, 0);

    for (int t = 0; t < NT; t++) {
        const int buf = t & 1;
        if (t + 1 < NT) {
            fill(buf ^ 1, (t + 1) * BK);
            asm volatile("cp.async.wait_group 1;" ::: "memory");
        } else {
            asm volatile("cp.async.wait_group 0;" ::: "memory");
        }
        __syncthreads();

        const uint32_t bb = sb + buf * BUFB;
        #pragma unroll
        for (int ks = 0; ks < 2; ks++) {           // two k16 steps per BK=32
            const int kc = ks * 2;
            uint32_t ah[4][4], al[4][4], bh[2][4], bl[2][4];
            #pragma unroll
            for (int tm = 0; tm < 4; tm++) {
                int row = wm * 64 + tm * 16 + (g & 1) * 8 + (lane & 7);
                uint32_t o = smem_off(row, kc + (g >> 1));
                ldsm4(ah[tm], bb + o);
                ldsm4(al[tm], bb + REG + o);
            }
            #pragma unroll
            for (int tp = 0; tp < 2; tp++) {
                int row = wn * 32 + tp * 16 + (g >> 1) * 8 + (lane & 7);
                uint32_t o = smem_off(row, kc + (g & 1));
                ldsm4(bh[tp], bb + 2 * REG + o);
                ldsm4(bl[tp], bb + 3 * REG + o);
            }
            // term-major: 16 independent MMAs between reuses of the same accumulator
            #pragma unroll
            for (int tm = 0; tm < 4; tm++)
                #pragma unroll
                for (int tn = 0; tn < 4; tn++)
                    mma16816(acc[tm][tn], ah[tm], &bh[tn >> 1][(tn & 1) * 2]);
            #pragma unroll
            for (int tm = 0; tm < 4; tm++)
                #pragma unroll
                for (int tn = 0; tn < 4; tn++)
                    mma16816(acc[tm][tn], ah[tm], &bl[tn >> 1][(tn & 1) * 2]);
            #pragma unroll
            for (int tm = 0; tm < 4; tm++)
                #pragma unroll
                for (int tn = 0; tn < 4; tn++)
                    mma16816(acc[tm][tn], al[tm], &bh[tn >> 1][(tn & 1) * 2]);
        }
        __syncthreads();
    }

    // ---------------- epilogue: bias + activation, store from registers ----------------
    #pragma unroll
    for (int tm = 0; tm < 4; tm++) {
        #pragma unroll
        for (int half = 0; half < 2; half++) {       // c0c1 (row) / c2c3 (row+8)
            const int m = m0 + wm * 64 + tm * 16 + half * 8 + (lane >> 2);
            if (m >= cnt) continue;
            float* orow = nullptr;
            __nv_bfloat16 *hrow = nullptr, *lrow = nullptr;
            if (DOWN) {
                orow = out + (size_t)g_list[e][m] * HDIM;
            } else {
                hrow = &g_Hh[e][m][0];
                lrow = &g_Hl[e][m][0];
            }
            #pragma unroll
            for (int tn = 0; tn < 4; tn++) {
                const int col = n0 + wn * 32 + tn * 8 + (lane & 3) * 2;
                #pragma unroll
                for (int q = 0; q < 2; q++) {
                    float v = acc[tm][tn][half * 2 + q] + bias[col + q];
                    if (ACT == ACT_GELU)
                        v = 0.5f * v * (1.0f + erff(v * 0.70710678118654752f));
                    else if (ACT == ACT_RELU)
                        v = fmaxf(v, 0.0f);
                    if (DOWN) {
                        orow[col + q] = v;
                    } else {
                        __nv_bfloat16 h = __float2bfloat16(v);
                        hrow[col + q] = h;
                        lrow[col + q] = __float2bfloat16(v - __bfloat162float(h));
                    }
                }
            }
        }
    }
}

// ---------------- launch ----------------
extern "C" void kernel_launch(void* const* d_in, const int* in_sizes, int n_in,
                              void* d_out, int out_size) {
    const float* x   = (const float*)d_in[0];
    const float* Wg  = (const float*)d_in[1];
    const float* W0a = (const float*)d_in[2];
    const float* b0a = (const float*)d_in[3];
    const float* W0b = (const float*)d_in[4];
    const float* b0b = (const float*)d_in[5];
    const float* W1a = (const float*)d_in[6];
    const float* b1a = (const float*)d_in[7];
    const float* W1b = (const float*)d_in[8];
    const float* b1b = (const float*)d_in[9];
    float* out = (float*)d_out;

    constexpr int SMEM_SZ = 2 * 32768;   // 64KB
    cudaFuncSetAttribute(moe_gemm<HDIM, ACT_GELU, false>,
                         cudaFuncAttributeMaxDynamicSharedMemorySize, SMEM_SZ);
    cudaFuncSetAttribute(moe_gemm<HDIM, ACT_RELU, false>,
                         cudaFuncAttributeMaxDynamicSharedMemorySize, SMEM_SZ);
    cudaFuncSetAttribute(moe_gemm<FDIM, ACT_NONE, true>,
                         cudaFuncAttributeMaxDynamicSharedMemorySize, SMEM_SZ);

    zero_counts_kernel<<<1, 32>>>();
    gate_gather_kernel<<<NTOK / 8, 256>>>(x, Wg);

    dim3 gW((FDIM * HDIM / 4) / 256, 4);
    wsplit_all_kernel<<<gW, 256>>>(W0a, W1a, W0b, W1b);

    dim3 gUp(FDIM / BN, NTOK / BM);   // (32, 64)
    dim3 gDn(HDIM / BN, NTOK / BM);   // (16, 64)
    moe_gemm<HDIM, ACT_GELU, false><<<gUp, GTHREADS, SMEM_SZ>>>(0, b0a, nullptr);
    moe_gemm<HDIM, ACT_RELU, false><<<gUp, GTHREADS, SMEM_SZ>>>(1, b1a, nullptr);
    moe_gemm<FDIM, ACT_NONE, true><<<gDn, GTHREADS, SMEM_SZ>>>(0, b0b, out);
    moe_gemm<FDIM, ACT_NONE, true><<<gDn, GTHREADS, SMEM_SZ>>>(1, b1b, out);
}

// round 6
// speedup vs baseline: 3.3252x; 1.0675x over previous
#include <cuda_runtime.h>
#include <cuda_bf16.h>
#include <math.h>
#include <stdint.h>

// ---------------- problem constants ----------------
#define HDIM 2048
#define FDIM 4096
#define NTOK 8192

// ---------------- GEMM tiling ----------------
#define BM 128
#define BN 128
#define BK 32               // bf16 elements per k-chunk
#define GTHREADS 256        // 8 warps: 2 (M) x 4 (N)
#define NSTAGE 3

// ---------------- device scratch (static globals; no allocation) ----------------
__device__ int g_cnt[2];
__device__ int g_list[2][NTOK];
__device__ __align__(128) __nv_bfloat16 g_Xh[2][NTOK][HDIM];
__device__ __align__(128) __nv_bfloat16 g_Xl[2][NTOK][HDIM];
__device__ __align__(128) __nv_bfloat16 g_Hh[2][NTOK][FDIM];
__device__ __align__(128) __nv_bfloat16 g_Hl[2][NTOK][FDIM];
__device__ __align__(128) __nv_bfloat16 g_Wah[2][FDIM][HDIM];
__device__ __align__(128) __nv_bfloat16 g_Wal[2][FDIM][HDIM];
__device__ __align__(128) __nv_bfloat16 g_Wbh[2][HDIM][FDIM];
__device__ __align__(128) __nv_bfloat16 g_Wbl[2][HDIM][FDIM];

// ---------------- PTX helpers (plain sm_80+ features only) ----------------
__device__ __forceinline__ void cpa16(uint32_t dst, const void* src) {
    asm volatile("cp.async.cg.shared.global [%0], [%1], 16;" :: "r"(dst), "l"(src));
}
__device__ __forceinline__ void ldsm4(uint32_t* r, uint32_t addr) {
    asm volatile("ldmatrix.sync.aligned.m8n8.x4.shared.b16 {%0,%1,%2,%3}, [%4];"
                 : "=r"(r[0]), "=r"(r[1]), "=r"(r[2]), "=r"(r[3]) : "r"(addr));
}
__device__ __forceinline__ void mma16816(float* c, const uint32_t* a, const uint32_t* b) {
    asm volatile("mma.sync.aligned.m16n8k16.row.col.f32.bf16.bf16.f32 "
                 "{%0,%1,%2,%3}, {%4,%5,%6,%7}, {%8,%9}, {%0,%1,%2,%3};"
                 : "+f"(c[0]), "+f"(c[1]), "+f"(c[2]), "+f"(c[3])
                 : "r"(a[0]), "r"(a[1]), "r"(a[2]), "r"(a[3]), "r"(b[0]), "r"(b[1]));
}

// smem tile layout: [128 rows][32 bf16] as 64 lines of 128B (2 rows/line),
// 8 x 16B chunks per line, chunk ^= (line & 7) -> conflict-free ldmatrix + cp.async
__device__ __forceinline__ uint32_t smem_off(int row, int kc /*16B chunk 0..3*/) {
    int line = row >> 1;
    int ch = ((row & 1) << 2) | kc;
    ch ^= (line & 7);
    return (uint32_t)(line * 128 + ch * 16);
}

// ---------------- kernel: zero counters ----------------
__global__ void zero_counts_kernel() {
    if (threadIdx.x < 2) g_cnt[threadIdx.x] = 0;
}

// ---------------- kernel: gate + compact + gather + bf16 split ----------------
__global__ void gate_gather_kernel(const float* __restrict__ x,
                                   const float* __restrict__ Wg) {
    __shared__ float wg[2 * HDIM];
    for (int i = threadIdx.x; i < 2 * HDIM; i += blockDim.x) wg[i] = Wg[i];
    __syncthreads();

    const int warp = threadIdx.x >> 5;
    const int lane = threadIdx.x & 31;
    const int token = blockIdx.x * 8 + warp;
    const float* xr = x + (size_t)token * HDIM;

    float s0 = 0.f, s1 = 0.f;
    for (int i = lane; i < HDIM; i += 32) {
        float v = xr[i];
        s0 += v * wg[i];
        s1 += v * wg[HDIM + i];
    }
    #pragma unroll
    for (int o = 16; o > 0; o >>= 1) {
        s0 += __shfl_xor_sync(0xffffffffu, s0, o);
        s1 += __shfl_xor_sync(0xffffffffu, s1, o);
    }
    const int e = (s1 > s0) ? 1 : 0;   // argmax(softmax)==argmax(logits); ties -> 0

    int pos = 0;
    if (lane == 0) pos = atomicAdd(&g_cnt[e], 1);
    pos = __shfl_sync(0xffffffffu, pos, 0);
    if (lane == 0) g_list[e][pos] = token;

    for (int i = lane; i < HDIM; i += 32) {
        float v = xr[i];
        __nv_bfloat16 h = __float2bfloat16(v);
        g_Xh[e][pos][i] = h;
        g_Xl[e][pos][i] = __float2bfloat16(v - __bfloat162float(h));
    }
}

// ---------------- kernel: all-weights split fp32 -> bf16 hi/lo (one launch) ----------------
__global__ void wsplit_all_kernel(const float* __restrict__ W0a, const float* __restrict__ W1a,
                                  const float* __restrict__ W0b, const float* __restrict__ W1b) {
    const int which = blockIdx.y;
    const float* src;
    __nv_bfloat16 *H, *L;
    switch (which) {
        case 0: src = W0a; H = &g_Wah[0][0][0]; L = &g_Wal[0][0][0]; break;
        case 1: src = W1a; H = &g_Wah[1][0][0]; L = &g_Wal[1][0][0]; break;
        case 2: src = W0b; H = &g_Wbh[0][0][0]; L = &g_Wbl[0][0][0]; break;
        default: src = W1b; H = &g_Wbh[1][0][0]; L = &g_Wbl[1][0][0]; break;
    }
    const size_t i = ((size_t)blockIdx.x * 256 + threadIdx.x) * 4;
    float4 v = *reinterpret_cast<const float4*>(src + i);
    float vv[4] = {v.x, v.y, v.z, v.w};
    __nv_bfloat16 hh[4], ll[4];
    #pragma unroll
    for (int j = 0; j < 4; j++) {
        hh[j] = __float2bfloat16(vv[j]);
        ll[j] = __float2bfloat16(vv[j] - __bfloat162float(hh[j]));
    }
    *reinterpret_cast<uint2*>(H + i) = *reinterpret_cast<uint2*>(hh);
    *reinterpret_cast<uint2*>(L + i) = *reinterpret_cast<uint2*>(ll);
}

// ---------------- kernel: split-bf16 mma.sync GEMM (both experts, 3-stage pipe) ----------------
// C[m,n] = sum_k A[m,k]*B[n,k], fp32 accum, via AhBh + AhBl + AlBh (term-major)
// blockIdx.z = expert. Up: act = e ? RELU : GELU. Down: scatter fp32 rows.
template <int K, bool DOWN>
__global__ void __launch_bounds__(GTHREADS, 2)
moe_gemm(const float* __restrict__ bias0, const float* __restrict__ bias1,
         float* __restrict__ out) {
    const int e = blockIdx.z;
    const int cnt = g_cnt[e];
    const int m0 = blockIdx.y * BM;
    if (m0 >= cnt) return;
    const int n0 = blockIdx.x * BN;
    const float* bias = e ? bias1 : bias0;

    extern __shared__ char smem[];
    const uint32_t sb = (uint32_t)__cvta_generic_to_shared(smem);

    const int tid = threadIdx.x;
    const int lane = tid & 31;
    const int warp = tid >> 5;
    const int wm = warp >> 2;          // 0..1  (64 rows each)
    const int wn = warp & 3;           // 0..3  (32 cols each)
    const int g = lane >> 3;           // ldmatrix lane group

    const __nv_bfloat16* Ah = DOWN ? &g_Hh[e][0][0] : &g_Xh[e][0][0];
    const __nv_bfloat16* Al = DOWN ? &g_Hl[e][0][0] : &g_Xl[e][0][0];
    const __nv_bfloat16* Bh = DOWN ? &g_Wbh[e][0][0] : &g_Wah[e][0][0];
    const __nv_bfloat16* Bl = DOWN ? &g_Wbl[e][0][0] : &g_Wal[e][0][0];
    const __nv_bfloat16* srcs[4] = {Ah, Al, Bh, Bl};

    // per-stage: Ah 8K | Al 8K | Bh 8K | Bl 8K = 32KB; 3 stages = 96KB
    constexpr uint32_t BUFB = 32768u;
    constexpr uint32_t REG = 8192u;

    auto fill = [&](int buf, int k0) {
        const uint32_t bb = sb + buf * BUFB;
        #pragma unroll
        for (int i = 0; i < 8; i++) {
            int idx = tid + i * 256;           // 0..2047
            int region = idx >> 9;             // 0..3
            int cid = idx & 511;
            int row = cid >> 2, kc = cid & 3;
            int grow = (region < 2) ? (m0 + row) : (n0 + row);
            const __nv_bfloat16* s = srcs[region] + (size_t)grow * K + k0 + kc * 8;
            cpa16(bb + region * REG + smem_off(row, kc), s);
        }
        asm volatile("cp.async.commit_group;" ::: "memory");
    };

    float acc[4][4][4];
    #pragma unroll
    for (int i = 0; i < 4; i++)
        #pragma unroll
        for (int j = 0; j < 4; j++)
            #pragma unroll
            for (int q = 0; q < 4; q++) acc[i][j][q] = 0.f;

    const int NT = K / BK;
    fill(0, 0);
    fill(1, BK);

    for (int t = 0; t < NT; t++) {
        const int buf = t % NSTAGE;
        // stage t must be complete; allow stage t+1 to remain in flight
        if (t + 1 < NT) {
            asm volatile("cp.async.wait_group 1;" ::: "memory");
        } else {
            asm volatile("cp.async.wait_group 0;" ::: "memory");
        }
        __syncthreads();   // all warps see stage t; also frees buffer (t-1)%3

        if (t + 2 < NT) fill((t + 2) % NSTAGE, (t + 2) * BK);

        const uint32_t bb = sb + buf * BUFB;
        #pragma unroll
        for (int ks = 0; ks < 2; ks++) {           // two k16 steps per BK=32
            const int kc = ks * 2;
            uint32_t ah[4][4], al[4][4], bh[2][4], bl[2][4];
            #pragma unroll
            for (int tm = 0; tm < 4; tm++) {
                int row = wm * 64 + tm * 16 + (g & 1) * 8 + (lane & 7);
                uint32_t o = smem_off(row, kc + (g >> 1));
                ldsm4(ah[tm], bb + o);
                ldsm4(al[tm], bb + REG + o);
            }
            #pragma unroll
            for (int tp = 0; tp < 2; tp++) {
                int row = wn * 32 + tp * 16 + (g >> 1) * 8 + (lane & 7);
                uint32_t o = smem_off(row, kc + (g & 1));
                ldsm4(bh[tp], bb + 2 * REG + o);
                ldsm4(bl[tp], bb + 3 * REG + o);
            }
            // term-major: 16 independent MMAs between reuses of the same accumulator
            #pragma unroll
            for (int tm = 0; tm < 4; tm++)
                #pragma unroll
                for (int tn = 0; tn < 4; tn++)
                    mma16816(acc[tm][tn], ah[tm], &bh[tn >> 1][(tn & 1) * 2]);
            #pragma unroll
            for (int tm = 0; tm < 4; tm++)
                #pragma unroll
                for (int tn = 0; tn < 4; tn++)
                    mma16816(acc[tm][tn], ah[tm], &bl[tn >> 1][(tn & 1) * 2]);
            #pragma unroll
            for (int tm = 0; tm < 4; tm++)
                #pragma unroll
                for (int tn = 0; tn < 4; tn++)
                    mma16816(acc[tm][tn], al[tm], &bh[tn >> 1][(tn & 1) * 2]);
        }
    }

    // ---------------- epilogue: bias + activation, store from registers ----------------
    const bool gelu = (!DOWN) && (e == 0);
    const bool relu = (!DOWN) && (e == 1);
    #pragma unroll
    for (int tm = 0; tm < 4; tm++) {
        #pragma unroll
        for (int half = 0; half < 2; half++) {       // c0c1 (row) / c2c3 (row+8)
            const int m = m0 + wm * 64 + tm * 16 + half * 8 + (lane >> 2);
            if (m >= cnt) continue;
            float* orow = nullptr;
            __nv_bfloat16 *hrow = nullptr, *lrow = nullptr;
            if (DOWN) {
                orow = out + (size_t)g_list[e][m] * HDIM;
            } else {
                hrow = &g_Hh[e][m][0];
                lrow = &g_Hl[e][m][0];
            }
            #pragma unroll
            for (int tn = 0; tn < 4; tn++) {
                const int col = n0 + wn * 32 + tn * 8 + (lane & 3) * 2;
                #pragma unroll
                for (int q = 0; q < 2; q++) {
                    float v = acc[tm][tn][half * 2 + q] + bias[col + q];
                    if (gelu)
                        v = 0.5f * v * (1.0f + erff(v * 0.70710678118654752f));
                    else if (relu)
                        v = fmaxf(v, 0.0f);
                    if (DOWN) {
                        orow[col + q] = v;
                    } else {
                        __nv_bfloat16 h = __float2bfloat16(v);
                        hrow[col + q] = h;
                        lrow[col + q] = __float2bfloat16(v - __bfloat162float(h));
                    }
                }
            }
        }
    }
}

// ---------------- launch ----------------
extern "C" void kernel_launch(void* const* d_in, const int* in_sizes, int n_in,
                              void* d_out, int out_size) {
    const float* x   = (const float*)d_in[0];
    const float* Wg  = (const float*)d_in[1];
    const float* W0a = (const float*)d_in[2];
    const float* b0a = (const float*)d_in[3];
    const float* W0b = (const float*)d_in[4];
    const float* b0b = (const float*)d_in[5];
    const float* W1a = (const float*)d_in[6];
    const float* b1a = (const float*)d_in[7];
    const float* W1b = (const float*)d_in[8];
    const float* b1b = (const float*)d_in[9];
    float* out = (float*)d_out;

    constexpr int SMEM_SZ = NSTAGE * 32768;   // 96KB
    cudaFuncSetAttribute(moe_gemm<HDIM, false>,
                         cudaFuncAttributeMaxDynamicSharedMemorySize, SMEM_SZ);
    cudaFuncSetAttribute(moe_gemm<FDIM, true>,
                         cudaFuncAttributeMaxDynamicSharedMemorySize, SMEM_SZ);

    zero_counts_kernel<<<1, 32>>>();
    gate_gather_kernel<<<NTOK / 8, 256>>>(x, Wg);

    dim3 gW((FDIM * HDIM / 4) / 256, 4);
    wsplit_all_kernel<<<gW, 256>>>(W0a, W1a, W0b, W1b);

    dim3 gUp(FDIM / BN, NTOK / BM, 2);   // (32, 64, 2)
    dim3 gDn(HDIM / BN, NTOK / BM, 2);   // (16, 64, 2)
    moe_gemm<HDIM, false><<<gUp, GTHREADS, SMEM_SZ>>>(b0a, b1a, nullptr);
    moe_gemm<FDIM, true><<<gDn, GTHREADS, SMEM_SZ>>>(b0b, b1b, out);
}

// round 7
// speedup vs baseline: 9.0910x; 2.7340x over previous
#include <cuda_runtime.h>
#include <cuda_fp16.h>
#include <math.h>
#include <stdint.h>

// ---------------- problem constants ----------------
#define HDIM 2048
#define FDIM 4096
#define NTOK 8192

// ---------------- GEMM tiling ----------------
#define BM 128
#define BN 128
#define BK 64               // fp16 elements per k-chunk (128B per row)
#define GTHREADS 256        // 8 warps: 2 (M) x 4 (N)
#define NSTAGE 3

// ---------------- device scratch (static globals; no allocation) ----------------
__device__ int g_cnt[2];
__device__ int g_list[2][NTOK];
__device__ __align__(128) __half g_X16[2][NTOK][HDIM];
__device__ __align__(128) __half g_H16[2][NTOK][FDIM];
__device__ __align__(128) __half g_Wa16[2][FDIM][HDIM];
__device__ __align__(128) __half g_Wb16[2][HDIM][FDIM];

// ---------------- PTX helpers (plain sm_80+ features only) ----------------
__device__ __forceinline__ void cpa16(uint32_t dst, const void* src) {
    asm volatile("cp.async.cg.shared.global [%0], [%1], 16;" :: "r"(dst), "l"(src));
}
__device__ __forceinline__ void ldsm4(uint32_t* r, uint32_t addr) {
    asm volatile("ldmatrix.sync.aligned.m8n8.x4.shared.b16 {%0,%1,%2,%3}, [%4];"
                 : "=r"(r[0]), "=r"(r[1]), "=r"(r[2]), "=r"(r[3]) : "r"(addr));
}
__device__ __forceinline__ void mma16816(float* c, const uint32_t* a, const uint32_t* b) {
    asm volatile("mma.sync.aligned.m16n8k16.row.col.f32.f16.f16.f32 "
                 "{%0,%1,%2,%3}, {%4,%5,%6,%7}, {%8,%9}, {%0,%1,%2,%3};"
                 : "+f"(c[0]), "+f"(c[1]), "+f"(c[2]), "+f"(c[3])
                 : "r"(a[0]), "r"(a[1]), "r"(a[2]), "r"(a[3]), "r"(b[0]), "r"(b[1]));
}

// smem tile: [128 rows][64 fp16] = 128B per row = 8 x 16B chunks,
// chunk ^= (row & 7)  -> conflict-free for ldmatrix groups and cp.async fills
__device__ __forceinline__ uint32_t smem_off(int row, int ch /*16B chunk 0..7*/) {
    return (uint32_t)(row * 128 + (ch ^ (row & 7)) * 16);
}

// ---------------- kernel: zero counters ----------------
__global__ void zero_counts_kernel() {
    if (threadIdx.x < 2) g_cnt[threadIdx.x] = 0;
}

// ---------------- kernel: gate + compact + gather(fp16) ----------------
__global__ void gate_gather_kernel(const float* __restrict__ x,
                                   const float* __restrict__ Wg) {
    __shared__ float wg[2 * HDIM];
    for (int i = threadIdx.x; i < 2 * HDIM; i += blockDim.x) wg[i] = Wg[i];
    __syncthreads();

    const int warp = threadIdx.x >> 5;
    const int lane = threadIdx.x & 31;
    const int token = blockIdx.x * 8 + warp;
    const float* xr = x + (size_t)token * HDIM;

    float s0 = 0.f, s1 = 0.f;
    for (int i = lane; i < HDIM; i += 32) {
        float v = xr[i];
        s0 += v * wg[i];
        s1 += v * wg[HDIM + i];
    }
    #pragma unroll
    for (int o = 16; o > 0; o >>= 1) {
        s0 += __shfl_xor_sync(0xffffffffu, s0, o);
        s1 += __shfl_xor_sync(0xffffffffu, s1, o);
    }
    const int e = (s1 > s0) ? 1 : 0;   // argmax(softmax)==argmax(logits); ties -> 0

    int pos = 0;
    if (lane == 0) pos = atomicAdd(&g_cnt[e], 1);
    pos = __shfl_sync(0xffffffffu, pos, 0);
    if (lane == 0) g_list[e][pos] = token;

    // gather + fp32->fp16, 4 elements per thread-iter (coalesced)
    for (int i = lane * 4; i < HDIM; i += 128) {
        float4 v = *reinterpret_cast<const float4*>(xr + i);
        __half h4[4] = {__float2half(v.x), __float2half(v.y),
                        __float2half(v.z), __float2half(v.w)};
        *reinterpret_cast<uint2*>(&g_X16[e][pos][i]) = *reinterpret_cast<uint2*>(h4);
    }
}

// ---------------- kernel: all weights fp32 -> fp16 (one launch) ----------------
__global__ void wconv_all_kernel(const float* __restrict__ W0a, const float* __restrict__ W1a,
                                 const float* __restrict__ W0b, const float* __restrict__ W1b) {
    const int which = blockIdx.y;
    const float* src;
    __half* dst;
    switch (which) {
        case 0: src = W0a; dst = &g_Wa16[0][0][0]; break;
        case 1: src = W1a; dst = &g_Wa16[1][0][0]; break;
        case 2: src = W0b; dst = &g_Wb16[0][0][0]; break;
        default: src = W1b; dst = &g_Wb16[1][0][0]; break;
    }
    const size_t i = ((size_t)blockIdx.x * 256 + threadIdx.x) * 4;
    float4 v = *reinterpret_cast<const float4*>(src + i);
    __half h4[4] = {__float2half(v.x), __float2half(v.y),
                    __float2half(v.z), __float2half(v.w)};
    *reinterpret_cast<uint2*>(dst + i) = *reinterpret_cast<uint2*>(h4);
}

// ---------------- kernel: fp16 mma.sync GEMM (both experts, 3-stage, BK=64) ----------------
// C[m,n] = sum_k A[m,k]*B[n,k], fp32 accum.
// blockIdx.z = expert. Up: act = e ? RELU : GELU, store fp16 h. Down: scatter fp32.
template <int K, bool DOWN>
__global__ void __launch_bounds__(GTHREADS, 2)
moe_gemm(const float* __restrict__ bias0, const float* __restrict__ bias1,
         float* __restrict__ out) {
    const int e = blockIdx.z;
    const int cnt = g_cnt[e];
    const int m0 = blockIdx.y * BM;
    if (m0 >= cnt) return;
    const int n0 = blockIdx.x * BN;
    const float* bias = e ? bias1 : bias0;

    extern __shared__ char smem[];
    const uint32_t sb = (uint32_t)__cvta_generic_to_shared(smem);

    const int tid = threadIdx.x;
    const int lane = tid & 31;
    const int warp = tid >> 5;
    const int wm = warp >> 2;          // 0..1  (64 rows each)
    const int wn = warp & 3;           // 0..3  (32 cols each)
    const int g = lane >> 3;           // ldmatrix lane group

    const __half* A = DOWN ? &g_H16[e][0][0] : &g_X16[e][0][0];
    const __half* B = DOWN ? &g_Wb16[e][0][0] : &g_Wa16[e][0][0];

    // per stage: A 16KB | B 16KB = 32KB; 3 stages = 96KB
    constexpr uint32_t BUFB = 32768u;
    constexpr uint32_t BREG = 16384u;

    auto fill = [&](int buf, int k0) {
        const uint32_t bb = sb + buf * BUFB;
        #pragma unroll
        for (int i = 0; i < 8; i++) {
            int idx = tid + i * 256;           // 0..2047 (16B chunks)
            int row = (idx & 1023) >> 3;
            int c = idx & 7;
            if (i < 4) {
                cpa16(bb + smem_off(row, c),
                      A + (size_t)(m0 + row) * K + k0 + c * 8);
            } else {
                cpa16(bb + BREG + smem_off(row, c),
                      B + (size_t)(n0 + row) * K + k0 + c * 8);
            }
        }
        asm volatile("cp.async.commit_group;" ::: "memory");
    };

    float acc[4][4][4];
    #pragma unroll
    for (int i = 0; i < 4; i++)
        #pragma unroll
        for (int j = 0; j < 4; j++)
            #pragma unroll
            for (int q = 0; q < 4; q++) acc[i][j][q] = 0.f;

    // fragment loaders (k16 step ks in 0..3 of current stage)
    auto load_a = [&](uint32_t bb, int ks, uint32_t af[4][4]) {
        #pragma unroll
        for (int tm = 0; tm < 4; tm++) {
            int row = wm * 64 + tm * 16 + (g & 1) * 8 + (lane & 7);
            ldsm4(af[tm], bb + smem_off(row, 2 * ks + (g >> 1)));
        }
    };
    auto load_b = [&](uint32_t bb, int ks, uint32_t bf[2][4]) {
        #pragma unroll
        for (int tp = 0; tp < 2; tp++) {
            int row = wn * 32 + tp * 16 + (g >> 1) * 8 + (lane & 7);
            ldsm4(bf[tp], bb + BREG + smem_off(row, 2 * ks + (g & 1)));
        }
    };

    const int NT = K / BK;
    fill(0, 0);
    fill(1, BK);

    uint32_t afA[4][4], afB[4][4], bfA[2][4], bfB[2][4];

    for (int t = 0; t < NT; t++) {
        const int buf = t % NSTAGE;
        if (t + 1 < NT) {
            asm volatile("cp.async.wait_group 1;" ::: "memory");
        } else {
            asm volatile("cp.async.wait_group 0;" ::: "memory");
        }
        __syncthreads();   // stage t visible; frees buffer (t-1)%3

        if (t + 2 < NT) fill((t + 2) % NSTAGE, (t + 2) * BK);

        const uint32_t bb = sb + buf * BUFB;
        load_a(bb, 0, afA);
        load_b(bb, 0, bfA);
        #pragma unroll
        for (int ks = 0; ks < 4; ks++) {
            uint32_t (*ac)[4] = (ks & 1) ? afB : afA;
            uint32_t (*bc)[4] = (ks & 1) ? bfB : bfA;
            uint32_t (*an)[4] = (ks & 1) ? afA : afB;
            uint32_t (*bn)[4] = (ks & 1) ? bfA : bfB;
            if (ks < 3) {                       // prefetch next k-step's frags
                load_a(bb, ks + 1, an);
                load_b(bb, ks + 1, bn);
            }
            #pragma unroll
            for (int tm = 0; tm < 4; tm++)
                #pragma unroll
                for (int tn = 0; tn < 4; tn++)
                    mma16816(acc[tm][tn], ac[tm], &bc[tn >> 1][(tn & 1) * 2]);
        }
    }

    // ---------------- epilogue: bias + activation ----------------
    const bool gelu = (!DOWN) && (e == 0);
    const bool relu = (!DOWN) && (e == 1);
    #pragma unroll
    for (int tm = 0; tm < 4; tm++) {
        #pragma unroll
        for (int half = 0; half < 2; half++) {       // c0c1 (row) / c2c3 (row+8)
            const int m = m0 + wm * 64 + tm * 16 + half * 8 + (lane >> 2);
            if (m >= cnt) continue;
            float* orow = nullptr;
            __half* hrow = nullptr;
            if (DOWN) {
                orow = out + (size_t)g_list[e][m] * HDIM;
            } else {
                hrow = &g_H16[e][m][0];
            }
            #pragma unroll
            for (int tn = 0; tn < 4; tn++) {
                const int col = n0 + wn * 32 + tn * 8 + (lane & 3) * 2;
                #pragma unroll
                for (int q = 0; q < 2; q++) {
                    float v = acc[tm][tn][half * 2 + q] + bias[col + q];
                    if (gelu)
                        v = 0.5f * v * (1.0f + erff(v * 0.70710678118654752f));
                    else if (relu)
                        v = fmaxf(v, 0.0f);
                    if (DOWN) orow[col + q] = v;
                    else      hrow[col + q] = __float2half(v);
                }
            }
        }
    }
}

// ---------------- launch ----------------
extern "C" void kernel_launch(void* const* d_in, const int* in_sizes, int n_in,
                              void* d_out, int out_size) {
    const float* x   = (const float*)d_in[0];
    const float* Wg  = (const float*)d_in[1];
    const float* W0a = (const float*)d_in[2];
    const float* b0a = (const float*)d_in[3];
    const float* W0b = (const float*)d_in[4];
    const float* b0b = (const float*)d_in[5];
    const float* W1a = (const float*)d_in[6];
    const float* b1a = (const float*)d_in[7];
    const float* W1b = (const float*)d_in[8];
    const float* b1b = (const float*)d_in[9];
    float* out = (float*)d_out;

    constexpr int SMEM_SZ = NSTAGE * 32768;   // 96KB
    cudaFuncSetAttribute(moe_gemm<HDIM, false>,
                         cudaFuncAttributeMaxDynamicSharedMemorySize, SMEM_SZ);
    cudaFuncSetAttribute(moe_gemm<FDIM, true>,
                         cudaFuncAttributeMaxDynamicSharedMemorySize, SMEM_SZ);

    zero_counts_kernel<<<1, 32>>>();
    gate_gather_kernel<<<NTOK / 8, 256>>>(x, Wg);

    dim3 gW((FDIM * HDIM / 4) / 256, 4);
    wconv_all_kernel<<<gW, 256>>>(W0a, W1a, W0b, W1b);

    dim3 gUp(FDIM / BN, NTOK / BM, 2);   // (32, 64, 2)
    dim3 gDn(HDIM / BN, NTOK / BM, 2);   // (16, 64, 2)
    moe_gemm<HDIM, false><<<gUp, GTHREADS, SMEM_SZ>>>(b0a, b1a, nullptr);
    moe_gemm<FDIM, true><<<gDn, GTHREADS, SMEM_SZ>>>(b0b, b1b, out);
}